// round 14
// baseline (speedup 1.0000x reference)
#include <cuda_runtime.h>
#include <cuda_fp16.h>
#include <stdint.h>
#include <math.h>

#define NB 4
#define NN 8192
#define KNN 16
#define DM 64
#define NPTS (NB * NN)   // 32768

__device__ float g_QKV[3][(size_t)NPTS * DM];
__device__ float g_res[(size_t)NPTS * DM];
__device__ float g_bf[3][DM];
// frag store: [mat 0..6][1024] uint2 = fp16 B fragment
// (mat: 0-2 folded fc1@{wq,wk,wv}, 3 d2, 4 g1, 5 g2, 6 fc2)
__device__ uint2 g_frag[7][1024];

// ---------------- fp16 helpers ----------------
__device__ __forceinline__ uint32_t pk_lohi(float lo, float hi) {
    uint32_t r;
    asm("cvt.rn.satfinite.f16x2.f32 %0, %1, %2;" : "=r"(r) : "f"(hi), "f"(lo));
    return r;
}
__device__ __forceinline__ void spack(float x0, float x1, uint32_t& hp, uint32_t& lp) {
    hp = pk_lohi(x0, x1);
    __half2 h = *reinterpret_cast<__half2*>(&hp);
    lp = pk_lohi(x0 - __half2float(h.x), x1 - __half2float(h.y));
}
__device__ __forceinline__ float frcp(float x) {
    float r;
    asm("rcp.approx.f32 %0, %1;" : "=f"(r) : "f"(x));
    return r;
}
__device__ __forceinline__ void mma_f16(float c[4], const uint32_t a[4], uint32_t b0, uint32_t b1) {
    asm volatile(
        "mma.sync.aligned.m16n8k16.row.col.f32.f16.f16.f32 "
        "{%0,%1,%2,%3},{%4,%5,%6,%7},{%8,%9},{%0,%1,%2,%3};"
        : "+f"(c[0]), "+f"(c[1]), "+f"(c[2]), "+f"(c[3])
        : "r"(a[0]), "r"(a[1]), "r"(a[2]), "r"(a[3]), "r"(b0), "r"(b1));
}

// 2-term stage: acc += A(16x64) * B(64x64); ONE LDS.64 per (j,t) feeds 2 mma
__device__ __forceinline__ void run_stage(float acc[8][4],
                                          const uint32_t ah[4][4], const uint32_t al[4][4],
                                          const uint2* __restrict__ B, int lane) {
    #pragma unroll
    for (int j = 0; j < 4; j++) {
        #pragma unroll
        for (int t = 0; t < 8; t++) {
            uint2 b = B[(j * 8 + t) * 32 + lane];
            mma_f16(acc[t], ah[j], b.x, b.y);
            mma_f16(acc[t], al[j], b.x, b.y);
        }
    }
}

// ================= prep: fold + all B fragments =================
__global__ void prep_kernel(const float* __restrict__ fc1_w, const float* __restrict__ fc1_b,
                            const float* __restrict__ wq, const float* __restrict__ wk,
                            const float* __restrict__ wv,
                            const float* __restrict__ d2w, const float* __restrict__ g1w,
                            const float* __restrict__ g2w, const float* __restrict__ fc2w) {
    int e = blockIdx.x * 256 + threadIdx.x;
    if (e < 7 * 1024) {
        int mat = e >> 10, r = e & 1023;
        int j = r >> 8, t = (r >> 5) & 7, ln = r & 31;
        int k0 = 16 * j + (ln & 3) * 2, n = 8 * t + (ln >> 2);
        float w00, w01, w10, w11;
        if (mat < 3) {
            const float* Wsel = (mat == 0) ? wq : ((mat == 1) ? wk : wv);
            float a0 = 0.f, a1 = 0.f, a2 = 0.f, a3 = 0.f;
            #pragma unroll 8
            for (int m = 0; m < 64; m++) {
                float wm = Wsel[m * 64 + n];
                a0 = fmaf(fc1_w[k0 * 64 + m], wm, a0);
                a1 = fmaf(fc1_w[(k0 + 1) * 64 + m], wm, a1);
                a2 = fmaf(fc1_w[(k0 + 8) * 64 + m], wm, a2);
                a3 = fmaf(fc1_w[(k0 + 9) * 64 + m], wm, a3);
            }
            w00 = a0; w01 = a1; w10 = a2; w11 = a3;
        } else {
            const float* W = (mat == 3) ? d2w : ((mat == 4) ? g1w : ((mat == 5) ? g2w : fc2w));
            w00 = W[k0 * 64 + n]; w01 = W[(k0 + 1) * 64 + n];
            w10 = W[(k0 + 8) * 64 + n]; w11 = W[(k0 + 9) * 64 + n];
        }
        uint2 rr;
        rr.x = pk_lohi(w00, w01);
        rr.y = pk_lohi(w10, w11);
        g_frag[mat][r] = rr;
    } else if (e < 7 * 1024 + 192) {
        int o = e - 7 * 1024, w = o >> 6, f = o & 63;
        const float* Wsel = (w == 0) ? wq : ((w == 1) ? wk : wv);
        float acc = 0.f;
        #pragma unroll 8
        for (int m = 0; m < 64; m++) acc = fmaf(fc1_b[m], Wsel[m * 64 + f], acc);
        g_bf[w][f] = acc;
    }
}

// ================= qkv3: Q/XK/XV via mma =================
struct SQ { uint2 bf[3][1024]; float bias[3][64]; };

__global__ __launch_bounds__(256, 2) void qkv3_kernel(const float* __restrict__ features) {
    extern __shared__ __align__(16) unsigned char smraw[];
    SQ* S = reinterpret_cast<SQ*>(smraw);
    const int tid = threadIdx.x;
    {
        const uint4* src = (const uint4*)&g_frag[0][0];
        uint4* dst = (uint4*)&S->bf[0][0];
        for (int i = tid; i < 1536; i += 256) dst[i] = src[i];
        for (int i = tid; i < 192; i += 256) S->bias[i >> 6][i & 63] = g_bf[i >> 6][i & 63];
    }
    __syncthreads();

    const int wid = tid >> 5, lane = tid & 31;
    const int r0 = lane >> 2, r1 = r0 + 8, cq = (lane & 3) * 2;
    const int m0 = blockIdx.x * 128 + wid * 16;

    uint32_t ah[4][4], al[4][4];
    const float* A0 = features + (size_t)(m0 + r0) * DM;
    const float* A1 = features + (size_t)(m0 + r1) * DM;
    #pragma unroll
    for (int j = 0; j < 4; j++) {
        int c = 16 * j + cq;
        float2 x00 = *(const float2*)(A0 + c);
        float2 x10 = *(const float2*)(A1 + c);
        float2 x01 = *(const float2*)(A0 + c + 8);
        float2 x11 = *(const float2*)(A1 + c + 8);
        spack(x00.x, x00.y, ah[j][0], al[j][0]);
        spack(x10.x, x10.y, ah[j][1], al[j][1]);
        spack(x01.x, x01.y, ah[j][2], al[j][2]);
        spack(x11.x, x11.y, ah[j][3], al[j][3]);
    }

    #pragma unroll
    for (int w = 0; w < 3; w++) {
        float acc[8][4];
        #pragma unroll
        for (int t = 0; t < 8; t++) { acc[t][0] = acc[t][1] = acc[t][2] = acc[t][3] = 0.f; }
        run_stage(acc, ah, al, &S->bf[w][0], lane);
        float* O = g_QKV[w];
        #pragma unroll
        for (int t = 0; t < 8; t++) {
            int c = 8 * t + cq;
            float b0 = S->bias[w][c], b1 = S->bias[w][c + 1];
            *(float2*)(O + (size_t)(m0 + r0) * DM + c) = make_float2(acc[t][0] + b0, acc[t][1] + b1);
            *(float2*)(O + (size_t)(m0 + r1) * DM + c) = make_float2(acc[t][2] + b0, acc[t][3] + b1);
        }
    }
}

// ================= fc2 via mma =================
struct SF { uint2 bf[1024]; float bias[64]; };

__global__ __launch_bounds__(256, 2) void fc2_kernel(const float* __restrict__ fc2b,
                                                     const float* __restrict__ features,
                                                     float* __restrict__ out) {
    extern __shared__ __align__(16) unsigned char smraw[];
    SF* S = reinterpret_cast<SF*>(smraw);
    const int tid = threadIdx.x;
    {
        const uint4* src = (const uint4*)&g_frag[6][0];
        uint4* dst = (uint4*)&S->bf[0];
        for (int i = tid; i < 512; i += 256) dst[i] = src[i];
        if (tid < 64) S->bias[tid] = fc2b[tid];
    }
    __syncthreads();

    const int wid = tid >> 5, lane = tid & 31;
    const int r0 = lane >> 2, r1 = r0 + 8, cq = (lane & 3) * 2;
    const int m0 = blockIdx.x * 128 + wid * 16;

    uint32_t ah[4][4], al[4][4];
    const float* A0 = g_res + (size_t)(m0 + r0) * DM;
    const float* A1 = g_res + (size_t)(m0 + r1) * DM;
    #pragma unroll
    for (int j = 0; j < 4; j++) {
        int c = 16 * j + cq;
        float2 x00 = *(const float2*)(A0 + c);
        float2 x10 = *(const float2*)(A1 + c);
        float2 x01 = *(const float2*)(A0 + c + 8);
        float2 x11 = *(const float2*)(A1 + c + 8);
        spack(x00.x, x00.y, ah[j][0], al[j][0]);
        spack(x10.x, x10.y, ah[j][1], al[j][1]);
        spack(x01.x, x01.y, ah[j][2], al[j][2]);
        spack(x11.x, x11.y, ah[j][3], al[j][3]);
    }
    float acc[8][4];
    #pragma unroll
    for (int t = 0; t < 8; t++) { acc[t][0] = acc[t][1] = acc[t][2] = acc[t][3] = 0.f; }
    run_stage(acc, ah, al, &S->bf[0], lane);
    #pragma unroll
    for (int t = 0; t < 8; t++) {
        int c = 8 * t + cq;
        float b0 = S->bias[c], b1 = S->bias[c + 1];
        float2 f0 = *(const float2*)(features + (size_t)(m0 + r0) * DM + c);
        float2 f1 = *(const float2*)(features + (size_t)(m0 + r1) * DM + c);
        *(float2*)(out + (size_t)(m0 + r0) * DM + c) = make_float2(acc[t][0] + b0 + f0.x, acc[t][1] + b1 + f0.y);
        *(float2*)(out + (size_t)(m0 + r1) * DM + c) = make_float2(acc[t][2] + b0 + f1.x, acc[t][3] + b1 + f1.y);
    }
}

// ================= main: fused per-neighbor transformer =================
struct SMemM {
    uint2 bf[3][1024];   // d2, g1, g2 (fp16)
    float d1[192];
    float bD1[64], bD2[64], bG1[64], bG2[64];
};

__global__ __launch_bounds__(256, 2) void main_kernel(
    const float* __restrict__ xyz, const int* __restrict__ knn,
    const float* __restrict__ d1w, const float* __restrict__ d1b,
    const float* __restrict__ d2b, const float* __restrict__ g1b,
    const float* __restrict__ g2b, float* __restrict__ out) {
    extern __shared__ __align__(16) unsigned char smraw[];
    SMemM* S = reinterpret_cast<SMemM*>(smraw);
    const int tid = threadIdx.x;
    {
        const uint4* src = (const uint4*)&g_frag[3][0];
        uint4* dst = (uint4*)&S->bf[0][0];
        for (int i = tid; i < 1536; i += 256) dst[i] = src[i];
    }
    for (int i = tid; i < 192; i += 256) S->d1[i] = d1w[i];
    if (tid < 64) {
        S->bD1[tid] = d1b[tid]; S->bD2[tid] = d2b[tid];
        S->bG1[tid] = g1b[tid]; S->bG2[tid] = g2b[tid];
    }
    __syncthreads();

    const int wid = tid >> 5, lane = tid & 31;
    const int r0 = lane >> 2, r1 = r0 + 8;
    const int cq = (lane & 3) * 2;
    float* __restrict__ attn_out = out + (size_t)NPTS * DM;
    const int stride = gridDim.x * 8;

    int m = blockIdx.x * 8 + wid;
    // ---- initial prefetch: indices + xyz for first iteration ----
    int pi0 = 0, pi1 = 0;
    float pxc = 0, pyc = 0, pzc = 0;
    float pn0x = 0, pn0y = 0, pn0z = 0, pn1x = 0, pn1y = 0, pn1z = 0;
    if (m < NPTS) {
        const int base = (m >> 13) * NN;
        pi0 = knn[m * KNN + r0];
        pi1 = knn[m * KNN + r1];
        pxc = xyz[3 * m]; pyc = xyz[3 * m + 1]; pzc = xyz[3 * m + 2];
        const float* n0 = xyz + (size_t)(base + pi0) * 3;
        const float* n1 = xyz + (size_t)(base + pi1) * 3;
        pn0x = n0[0]; pn0y = n0[1]; pn0z = n0[2];
        pn1x = n1[0]; pn1y = n1[1]; pn1z = n1[2];
    }

    for (; m < NPTS; m += stride) {
        const int base = (m >> 13) * NN;
        const int i0 = pi0, i1 = pi1;
        const float rx0 = pxc - pn0x, ry0 = pyc - pn0y, rz0 = pzc - pn0z;
        const float rx1 = pxc - pn1x, ry1 = pyc - pn1y, rz1 = pzc - pn1z;
        const int mn = m + stride;
        // prefetch next iteration's knn rows (2-hop chain starts now)
        if (mn < NPTS) {
            pi0 = knn[mn * KNN + r0];
            pi1 = knn[mn * KNN + r1];
        }

        // issue Q-row and K-row loads up front; consumed after stage 1
        const float* Qrow = g_QKV[0] + (size_t)m * DM;
        const float* Kr0p = g_QKV[1] + (size_t)(base + i0) * DM;
        const float* Kr1p = g_QKV[1] + (size_t)(base + i1) * DM;
        float2 qb[8], kb0[8], kb1[8];
        #pragma unroll
        for (int t = 0; t < 8; t++) {
            qb[t]  = *(const float2*)(Qrow + 8 * t + cq);
            kb0[t] = *(const float2*)(Kr0p + 8 * t + cq);
            kb1[t] = *(const float2*)(Kr1p + 8 * t + cq);
        }

        uint32_t ah[4][4], al[4][4];
        // ---- t = relu(rel @ d1 + d1b) in frag layout ----
        #pragma unroll
        for (int j = 0; j < 4; j++) {
            #pragma unroll
            for (int half = 0; half < 2; half++) {
                int c = 16 * j + 8 * half + cq;
                float b0 = S->bD1[c], b1 = S->bD1[c + 1];
                float wx0 = S->d1[c], wy0 = S->d1[64 + c], wz0 = S->d1[128 + c];
                float wx1 = S->d1[c + 1], wy1 = S->d1[65 + c], wz1 = S->d1[129 + c];
                float t00 = fmaxf(fmaf(rz0, wz0, fmaf(ry0, wy0, fmaf(rx0, wx0, b0))), 0.f);
                float t01 = fmaxf(fmaf(rz0, wz1, fmaf(ry0, wy1, fmaf(rx0, wx1, b1))), 0.f);
                float t10 = fmaxf(fmaf(rz1, wz0, fmaf(ry1, wy0, fmaf(rx1, wx0, b0))), 0.f);
                float t11 = fmaxf(fmaf(rz1, wz1, fmaf(ry1, wy1, fmaf(rx1, wx1, b1))), 0.f);
                spack(t00, t01, ah[j][2 * half], al[j][2 * half]);
                spack(t10, t11, ah[j][2 * half + 1], al[j][2 * half + 1]);
            }
        }
        float acc[8][4];
        #pragma unroll
        for (int t = 0; t < 8; t++) { acc[t][0] = acc[t][1] = acc[t][2] = acc[t][3] = 0.f; }
        run_stage(acc, ah, al, &S->bf[0][0], lane);

        // ---- pos = D + d2b ----
        float pos[8][4];
        #pragma unroll
        for (int t = 0; t < 8; t++) {
            int c = 8 * t + cq;
            float b0 = S->bD2[c], b1 = S->bD2[c + 1];
            pos[t][0] = acc[t][0] + b0; pos[t][1] = acc[t][1] + b1;
            pos[t][2] = acc[t][2] + b0; pos[t][3] = acc[t][3] + b1;
        }

        // ---- h = q - k + pos (q/k already in registers) ----
        #pragma unroll
        for (int j = 0; j < 4; j++) {
            #pragma unroll
            for (int half = 0; half < 2; half++) {
                int t = 2 * j + half;
                float h00 = qb[t].x - kb0[t].x + pos[t][0];
                float h01 = qb[t].y - kb0[t].y + pos[t][1];
                float h10 = qb[t].x - kb1[t].x + pos[t][2];
                float h11 = qb[t].y - kb1[t].y + pos[t][3];
                spack(h00, h01, ah[j][2 * half], al[j][2 * half]);
                spack(h10, h11, ah[j][2 * half + 1], al[j][2 * half + 1]);
            }
        }
        #pragma unroll
        for (int t = 0; t < 8; t++) { acc[t][0] = acc[t][1] = acc[t][2] = acc[t][3] = 0.f; }
        run_stage(acc, ah, al, &S->bf[1][0], lane);

        // ---- u = relu(D + g1b) ----
        #pragma unroll
        for (int j = 0; j < 4; j++) {
            #pragma unroll
            for (int half = 0; half < 2; half++) {
                int t = 2 * j + half;
                int c = 8 * t + cq;
                float b0 = S->bG1[c], b1 = S->bG1[c + 1];
                float u00 = fmaxf(acc[t][0] + b0, 0.f), u01 = fmaxf(acc[t][1] + b1, 0.f);
                float u10 = fmaxf(acc[t][2] + b0, 0.f), u11 = fmaxf(acc[t][3] + b1, 0.f);
                spack(u00, u01, ah[j][2 * half], al[j][2 * half]);
                spack(u10, u11, ah[j][2 * half + 1], al[j][2 * half + 1]);
            }
        }
        // ---- hoist V gathers: issued here, covered by stage-3 MMAs ----
        const float* Vr0 = g_QKV[2] + (size_t)(base + i0) * DM;
        const float* Vr1 = g_QKV[2] + (size_t)(base + i1) * DM;
        float2 vb0[8], vb1[8];
        #pragma unroll
        for (int t = 0; t < 8; t++) {
            vb0[t] = *(const float2*)(Vr0 + 8 * t + cq);
            vb1[t] = *(const float2*)(Vr1 + 8 * t + cq);
        }
        #pragma unroll
        for (int t = 0; t < 8; t++) { acc[t][0] = acc[t][1] = acc[t][2] = acc[t][3] = 0.f; }
        run_stage(acc, ah, al, &S->bf[2][0], lane);

        // ---- prefetch next iteration's xyz (uses new pi0/pi1) ----
        if (mn < NPTS) {
            const int nbase = (mn >> 13) * NN;
            pxc = xyz[3 * mn]; pyc = xyz[3 * mn + 1]; pzc = xyz[3 * mn + 2];
            const float* n0 = xyz + (size_t)(nbase + pi0) * 3;
            const float* n1 = xyz + (size_t)(nbase + pi1) * 3;
            pn0x = n0[0]; pn0y = n0[1]; pn0z = n0[2];
            pn1x = n1[0]; pn1y = n1[1]; pn1z = n1[2];
        }

        // ---- softmax over neighbors (no max subtraction; fp32 exp safe) ----
        {
            float* ao = attn_out + (size_t)m * (KNN * DM);
            float* ro = g_res + (size_t)m * DM;
            #pragma unroll
            for (int t = 0; t < 8; t++) {
                int c = 8 * t + cq;
                float b0 = S->bG2[c], b1 = S->bG2[c + 1];
                float e00 = __expf((acc[t][0] + b0) * 0.125f);
                float e01 = __expf((acc[t][1] + b1) * 0.125f);
                float e10 = __expf((acc[t][2] + b0) * 0.125f);
                float e11 = __expf((acc[t][3] + b1) * 0.125f);
                float s0 = e00 + e10, s1 = e01 + e11;
                #pragma unroll
                for (int o = 4; o < 32; o <<= 1) {
                    s0 += __shfl_xor_sync(0xffffffffu, s0, o);
                    s1 += __shfl_xor_sync(0xffffffffu, s1, o);
                }
                float inv0 = frcp(s0), inv1 = frcp(s1);
                float a00 = e00 * inv0, a01 = e01 * inv1;
                float a10 = e10 * inv0, a11 = e11 * inv1;
                *(float2*)(ao + r0 * DM + c) = make_float2(a00, a01);
                *(float2*)(ao + r1 * DM + c) = make_float2(a10, a11);
                float rc0 = a00 * (vb0[t].x + pos[t][0]) + a10 * (vb1[t].x + pos[t][2]);
                float rc1 = a01 * (vb0[t].y + pos[t][1]) + a11 * (vb1[t].y + pos[t][3]);
                #pragma unroll
                for (int o = 4; o < 32; o <<= 1) {
                    rc0 += __shfl_xor_sync(0xffffffffu, rc0, o);
                    rc1 += __shfl_xor_sync(0xffffffffu, rc1, o);
                }
                if (lane < 4) *(float2*)(ro + c) = make_float2(rc0, rc1);
            }
        }
    }
}

// ================= launch =================
extern "C" void kernel_launch(void* const* d_in, const int* in_sizes, int n_in,
                              void* d_out, int out_size) {
    const float* xyz      = (const float*)d_in[0];
    const float* features = (const float*)d_in[1];
    const int*   knn      = (const int*)d_in[2];
    const float* fc1_w    = (const float*)d_in[3];
    const float* fc1_b    = (const float*)d_in[4];
    const float* fc2_w    = (const float*)d_in[5];
    const float* fc2_b    = (const float*)d_in[6];
    const float* d1_w     = (const float*)d_in[7];
    const float* d1_b     = (const float*)d_in[8];
    const float* d2_w     = (const float*)d_in[9];
    const float* d2_b     = (const float*)d_in[10];
    const float* g1_w     = (const float*)d_in[11];
    const float* g1_b     = (const float*)d_in[12];
    const float* g2_w     = (const float*)d_in[13];
    const float* g2_b     = (const float*)d_in[14];
    const float* wq       = (const float*)d_in[15];
    const float* wk       = (const float*)d_in[16];
    const float* wv       = (const float*)d_in[17];
    float* out = (float*)d_out;

    prep_kernel<<<29, 256>>>(fc1_w, fc1_b, wq, wk, wv, d2_w, g1_w, g2_w, fc2_w);

    cudaFuncSetAttribute(qkv3_kernel, cudaFuncAttributeMaxDynamicSharedMemorySize, (int)sizeof(SQ));
    qkv3_kernel<<<NPTS / 128, 256, sizeof(SQ)>>>(features);

    cudaFuncSetAttribute(main_kernel, cudaFuncAttributeMaxDynamicSharedMemorySize, (int)sizeof(SMemM));
    main_kernel<<<296, 256, sizeof(SMemM)>>>(xyz, knn, d1_w, d1_b, d2_b, g1_b, g2_b, out);

    cudaFuncSetAttribute(fc2_kernel, cudaFuncAttributeMaxDynamicSharedMemorySize, (int)sizeof(SF));
    fc2_kernel<<<NPTS / 128, 256, sizeof(SF)>>>(fc2_b, features, out);
}

// round 15
// speedup vs baseline: 1.4980x; 1.4980x over previous
#include <cuda_runtime.h>
#include <cuda_fp16.h>
#include <stdint.h>
#include <math.h>

#define NB 4
#define NN 8192
#define KNN 16
#define DM 64
#define NPTS (NB * NN)   // 32768

__device__ float g_QKV[3][(size_t)NPTS * DM];
__device__ float g_res[(size_t)NPTS * DM];
__device__ float g_bf[3][DM];
// frag store: [mat 0..6][1024] uint2 = fp16 B fragment
// (mat: 0-2 folded fc1@{wq,wk,wv}, 3 d2, 4 g1, 5 g2, 6 fc2)
__device__ uint2 g_frag[7][1024];

// ---------------- fp16 helpers ----------------
__device__ __forceinline__ uint32_t pk_lohi(float lo, float hi) {
    uint32_t r;
    asm("cvt.rn.satfinite.f16x2.f32 %0, %1, %2;" : "=r"(r) : "f"(hi), "f"(lo));
    return r;
}
__device__ __forceinline__ void spack(float x0, float x1, uint32_t& hp, uint32_t& lp) {
    hp = pk_lohi(x0, x1);
    __half2 h = *reinterpret_cast<__half2*>(&hp);
    lp = pk_lohi(x0 - __half2float(h.x), x1 - __half2float(h.y));
}
__device__ __forceinline__ float frcp(float x) {
    float r;
    asm("rcp.approx.f32 %0, %1;" : "=f"(r) : "f"(x));
    return r;
}
__device__ __forceinline__ void mma_f16(float c[4], const uint32_t a[4], uint32_t b0, uint32_t b1) {
    asm volatile(
        "mma.sync.aligned.m16n8k16.row.col.f32.f16.f16.f32 "
        "{%0,%1,%2,%3},{%4,%5,%6,%7},{%8,%9},{%0,%1,%2,%3};"
        : "+f"(c[0]), "+f"(c[1]), "+f"(c[2]), "+f"(c[3])
        : "r"(a[0]), "r"(a[1]), "r"(a[2]), "r"(a[3]), "r"(b0), "r"(b1));
}

// 2-term stage: acc += A(16x64) * B(64x64); ONE LDS.64 per (j,t) feeds 2 mma
__device__ __forceinline__ void run_stage(float acc[8][4],
                                          const uint32_t ah[4][4], const uint32_t al[4][4],
                                          const uint2* __restrict__ B, int lane) {
    #pragma unroll
    for (int j = 0; j < 4; j++) {
        #pragma unroll
        for (int t = 0; t < 8; t++) {
            uint2 b = B[(j * 8 + t) * 32 + lane];
            mma_f16(acc[t], ah[j], b.x, b.y);
            mma_f16(acc[t], al[j], b.x, b.y);
        }
    }
}

// ================= prep: fold + all B fragments =================
__global__ void prep_kernel(const float* __restrict__ fc1_w, const float* __restrict__ fc1_b,
                            const float* __restrict__ wq, const float* __restrict__ wk,
                            const float* __restrict__ wv,
                            const float* __restrict__ d2w, const float* __restrict__ g1w,
                            const float* __restrict__ g2w, const float* __restrict__ fc2w) {
    int e = blockIdx.x * 256 + threadIdx.x;
    if (e < 7 * 1024) {
        int mat = e >> 10, r = e & 1023;
        int j = r >> 8, t = (r >> 5) & 7, ln = r & 31;
        int k0 = 16 * j + (ln & 3) * 2, n = 8 * t + (ln >> 2);
        float w00, w01, w10, w11;
        if (mat < 3) {
            const float* Wsel = (mat == 0) ? wq : ((mat == 1) ? wk : wv);
            float a0 = 0.f, a1 = 0.f, a2 = 0.f, a3 = 0.f;
            #pragma unroll 8
            for (int m = 0; m < 64; m++) {
                float wm = Wsel[m * 64 + n];
                a0 = fmaf(fc1_w[k0 * 64 + m], wm, a0);
                a1 = fmaf(fc1_w[(k0 + 1) * 64 + m], wm, a1);
                a2 = fmaf(fc1_w[(k0 + 8) * 64 + m], wm, a2);
                a3 = fmaf(fc1_w[(k0 + 9) * 64 + m], wm, a3);
            }
            w00 = a0; w01 = a1; w10 = a2; w11 = a3;
        } else {
            const float* W = (mat == 3) ? d2w : ((mat == 4) ? g1w : ((mat == 5) ? g2w : fc2w));
            w00 = W[k0 * 64 + n]; w01 = W[(k0 + 1) * 64 + n];
            w10 = W[(k0 + 8) * 64 + n]; w11 = W[(k0 + 9) * 64 + n];
        }
        uint2 rr;
        rr.x = pk_lohi(w00, w01);
        rr.y = pk_lohi(w10, w11);
        g_frag[mat][r] = rr;
    } else if (e < 7 * 1024 + 192) {
        int o = e - 7 * 1024, w = o >> 6, f = o & 63;
        const float* Wsel = (w == 0) ? wq : ((w == 1) ? wk : wv);
        float acc = 0.f;
        #pragma unroll 8
        for (int m = 0; m < 64; m++) acc = fmaf(fc1_b[m], Wsel[m * 64 + f], acc);
        g_bf[w][f] = acc;
    }
}

// ================= qkv3: Q/XK/XV via mma =================
struct SQ { uint2 bf[3][1024]; float bias[3][64]; };

__global__ __launch_bounds__(256, 2) void qkv3_kernel(const float* __restrict__ features) {
    extern __shared__ __align__(16) unsigned char smraw[];
    SQ* S = reinterpret_cast<SQ*>(smraw);
    const int tid = threadIdx.x;
    {
        const uint4* src = (const uint4*)&g_frag[0][0];
        uint4* dst = (uint4*)&S->bf[0][0];
        for (int i = tid; i < 1536; i += 256) dst[i] = src[i];
        for (int i = tid; i < 192; i += 256) S->bias[i >> 6][i & 63] = g_bf[i >> 6][i & 63];
    }
    __syncthreads();

    const int wid = tid >> 5, lane = tid & 31;
    const int r0 = lane >> 2, r1 = r0 + 8, cq = (lane & 3) * 2;
    const int m0 = blockIdx.x * 128 + wid * 16;

    uint32_t ah[4][4], al[4][4];
    const float* A0 = features + (size_t)(m0 + r0) * DM;
    const float* A1 = features + (size_t)(m0 + r1) * DM;
    #pragma unroll
    for (int j = 0; j < 4; j++) {
        int c = 16 * j + cq;
        float2 x00 = *(const float2*)(A0 + c);
        float2 x10 = *(const float2*)(A1 + c);
        float2 x01 = *(const float2*)(A0 + c + 8);
        float2 x11 = *(const float2*)(A1 + c + 8);
        spack(x00.x, x00.y, ah[j][0], al[j][0]);
        spack(x10.x, x10.y, ah[j][1], al[j][1]);
        spack(x01.x, x01.y, ah[j][2], al[j][2]);
        spack(x11.x, x11.y, ah[j][3], al[j][3]);
    }

    #pragma unroll
    for (int w = 0; w < 3; w++) {
        float acc[8][4];
        #pragma unroll
        for (int t = 0; t < 8; t++) { acc[t][0] = acc[t][1] = acc[t][2] = acc[t][3] = 0.f; }
        run_stage(acc, ah, al, &S->bf[w][0], lane);
        float* O = g_QKV[w];
        #pragma unroll
        for (int t = 0; t < 8; t++) {
            int c = 8 * t + cq;
            float b0 = S->bias[w][c], b1 = S->bias[w][c + 1];
            *(float2*)(O + (size_t)(m0 + r0) * DM + c) = make_float2(acc[t][0] + b0, acc[t][1] + b1);
            *(float2*)(O + (size_t)(m0 + r1) * DM + c) = make_float2(acc[t][2] + b0, acc[t][3] + b1);
        }
    }
}

// ================= fc2 via mma =================
struct SF { uint2 bf[1024]; float bias[64]; };

__global__ __launch_bounds__(256, 2) void fc2_kernel(const float* __restrict__ fc2b,
                                                     const float* __restrict__ features,
                                                     float* __restrict__ out) {
    extern __shared__ __align__(16) unsigned char smraw[];
    SF* S = reinterpret_cast<SF*>(smraw);
    const int tid = threadIdx.x;
    {
        const uint4* src = (const uint4*)&g_frag[6][0];
        uint4* dst = (uint4*)&S->bf[0];
        for (int i = tid; i < 512; i += 256) dst[i] = src[i];
        if (tid < 64) S->bias[tid] = fc2b[tid];
    }
    __syncthreads();

    const int wid = tid >> 5, lane = tid & 31;
    const int r0 = lane >> 2, r1 = r0 + 8, cq = (lane & 3) * 2;
    const int m0 = blockIdx.x * 128 + wid * 16;

    uint32_t ah[4][4], al[4][4];
    const float* A0 = g_res + (size_t)(m0 + r0) * DM;
    const float* A1 = g_res + (size_t)(m0 + r1) * DM;
    #pragma unroll
    for (int j = 0; j < 4; j++) {
        int c = 16 * j + cq;
        float2 x00 = *(const float2*)(A0 + c);
        float2 x10 = *(const float2*)(A1 + c);
        float2 x01 = *(const float2*)(A0 + c + 8);
        float2 x11 = *(const float2*)(A1 + c + 8);
        spack(x00.x, x00.y, ah[j][0], al[j][0]);
        spack(x10.x, x10.y, ah[j][1], al[j][1]);
        spack(x01.x, x01.y, ah[j][2], al[j][2]);
        spack(x11.x, x11.y, ah[j][3], al[j][3]);
    }
    float acc[8][4];
    #pragma unroll
    for (int t = 0; t < 8; t++) { acc[t][0] = acc[t][1] = acc[t][2] = acc[t][3] = 0.f; }
    run_stage(acc, ah, al, &S->bf[0], lane);
    #pragma unroll
    for (int t = 0; t < 8; t++) {
        int c = 8 * t + cq;
        float b0 = S->bias[c], b1 = S->bias[c + 1];
        float2 f0 = *(const float2*)(features + (size_t)(m0 + r0) * DM + c);
        float2 f1 = *(const float2*)(features + (size_t)(m0 + r1) * DM + c);
        *(float2*)(out + (size_t)(m0 + r0) * DM + c) = make_float2(acc[t][0] + b0 + f0.x, acc[t][1] + b1 + f0.y);
        *(float2*)(out + (size_t)(m0 + r1) * DM + c) = make_float2(acc[t][2] + b0 + f1.x, acc[t][3] + b1 + f1.y);
    }
}

// ================= main: fused per-neighbor transformer =================
struct SMemM {
    uint2 bf[3][1024];   // d2, g1, g2 (fp16)
    float d1[192];
    float bD1[64], bD2[64], bG1[64], bG2[64];
};

__global__ __launch_bounds__(256, 2) void main_kernel(
    const float* __restrict__ xyz, const int* __restrict__ knn,
    const float* __restrict__ d1w, const float* __restrict__ d1b,
    const float* __restrict__ d2b, const float* __restrict__ g1b,
    const float* __restrict__ g2b, float* __restrict__ out) {
    extern __shared__ __align__(16) unsigned char smraw[];
    SMemM* S = reinterpret_cast<SMemM*>(smraw);
    const int tid = threadIdx.x;
    {
        const uint4* src = (const uint4*)&g_frag[3][0];
        uint4* dst = (uint4*)&S->bf[0][0];
        for (int i = tid; i < 1536; i += 256) dst[i] = src[i];
    }
    for (int i = tid; i < 192; i += 256) S->d1[i] = d1w[i];
    if (tid < 64) {
        S->bD1[tid] = d1b[tid]; S->bD2[tid] = d2b[tid];
        S->bG1[tid] = g1b[tid]; S->bG2[tid] = g2b[tid];
    }
    __syncthreads();

    const int wid = tid >> 5, lane = tid & 31;
    const int r0 = lane >> 2, r1 = r0 + 8;
    const int cq = (lane & 3) * 2;
    float* __restrict__ attn_out = out + (size_t)NPTS * DM;
    const int stride = gridDim.x * 8;

    int m = blockIdx.x * 8 + wid;
    // ---- initial prefetch: indices + xyz for first iteration ----
    int pi0 = 0, pi1 = 0;
    float pxc = 0, pyc = 0, pzc = 0;
    float pn0x = 0, pn0y = 0, pn0z = 0, pn1x = 0, pn1y = 0, pn1z = 0;
    if (m < NPTS) {
        const int base = (m >> 13) * NN;
        pi0 = knn[m * KNN + r0];
        pi1 = knn[m * KNN + r1];
        pxc = xyz[3 * m]; pyc = xyz[3 * m + 1]; pzc = xyz[3 * m + 2];
        const float* n0 = xyz + (size_t)(base + pi0) * 3;
        const float* n1 = xyz + (size_t)(base + pi1) * 3;
        pn0x = n0[0]; pn0y = n0[1]; pn0z = n0[2];
        pn1x = n1[0]; pn1y = n1[1]; pn1z = n1[2];
    }

    for (; m < NPTS; m += stride) {
        const int base = (m >> 13) * NN;
        const int i0 = pi0, i1 = pi1;
        const float rx0 = pxc - pn0x, ry0 = pyc - pn0y, rz0 = pzc - pn0z;
        const float rx1 = pxc - pn1x, ry1 = pyc - pn1y, rz1 = pzc - pn1z;
        const int mn = m + stride;
        // prefetch next iteration's knn rows (2-hop chain starts now)
        if (mn < NPTS) {
            pi0 = knn[mn * KNN + r0];
            pi1 = knn[mn * KNN + r1];
        }

        // issue Q-row and K-row loads up front; consumed after stage 1
        const float* Qrow = g_QKV[0] + (size_t)m * DM;
        const float* Kr0p = g_QKV[1] + (size_t)(base + i0) * DM;
        const float* Kr1p = g_QKV[1] + (size_t)(base + i1) * DM;
        float2 qb[8], kb0[8], kb1[8];
        #pragma unroll
        for (int t = 0; t < 8; t++) {
            qb[t]  = *(const float2*)(Qrow + 8 * t + cq);
            kb0[t] = *(const float2*)(Kr0p + 8 * t + cq);
            kb1[t] = *(const float2*)(Kr1p + 8 * t + cq);
        }

        uint32_t ah[4][4], al[4][4];
        // ---- t = relu(rel @ d1 + d1b) in frag layout ----
        #pragma unroll
        for (int j = 0; j < 4; j++) {
            #pragma unroll
            for (int half = 0; half < 2; half++) {
                int c = 16 * j + 8 * half + cq;
                float b0 = S->bD1[c], b1 = S->bD1[c + 1];
                float wx0 = S->d1[c], wy0 = S->d1[64 + c], wz0 = S->d1[128 + c];
                float wx1 = S->d1[c + 1], wy1 = S->d1[65 + c], wz1 = S->d1[129 + c];
                float t00 = fmaxf(fmaf(rz0, wz0, fmaf(ry0, wy0, fmaf(rx0, wx0, b0))), 0.f);
                float t01 = fmaxf(fmaf(rz0, wz1, fmaf(ry0, wy1, fmaf(rx0, wx1, b1))), 0.f);
                float t10 = fmaxf(fmaf(rz1, wz0, fmaf(ry1, wy0, fmaf(rx1, wx0, b0))), 0.f);
                float t11 = fmaxf(fmaf(rz1, wz1, fmaf(ry1, wy1, fmaf(rx1, wx1, b1))), 0.f);
                spack(t00, t01, ah[j][2 * half], al[j][2 * half]);
                spack(t10, t11, ah[j][2 * half + 1], al[j][2 * half + 1]);
            }
        }
        float acc[8][4];
        #pragma unroll
        for (int t = 0; t < 8; t++) { acc[t][0] = acc[t][1] = acc[t][2] = acc[t][3] = 0.f; }
        run_stage(acc, ah, al, &S->bf[0][0], lane);

        // ---- pos = D + d2b ----
        float pos[8][4];
        #pragma unroll
        for (int t = 0; t < 8; t++) {
            int c = 8 * t + cq;
            float b0 = S->bD2[c], b1 = S->bD2[c + 1];
            pos[t][0] = acc[t][0] + b0; pos[t][1] = acc[t][1] + b1;
            pos[t][2] = acc[t][2] + b0; pos[t][3] = acc[t][3] + b1;
        }

        // ---- h = q - k + pos (q/k already in registers) ----
        #pragma unroll
        for (int j = 0; j < 4; j++) {
            #pragma unroll
            for (int half = 0; half < 2; half++) {
                int t = 2 * j + half;
                float h00 = qb[t].x - kb0[t].x + pos[t][0];
                float h01 = qb[t].y - kb0[t].y + pos[t][1];
                float h10 = qb[t].x - kb1[t].x + pos[t][2];
                float h11 = qb[t].y - kb1[t].y + pos[t][3];
                spack(h00, h01, ah[j][2 * half], al[j][2 * half]);
                spack(h10, h11, ah[j][2 * half + 1], al[j][2 * half + 1]);
            }
        }
        #pragma unroll
        for (int t = 0; t < 8; t++) { acc[t][0] = acc[t][1] = acc[t][2] = acc[t][3] = 0.f; }
        run_stage(acc, ah, al, &S->bf[1][0], lane);

        // ---- u = relu(D + g1b) ----
        #pragma unroll
        for (int j = 0; j < 4; j++) {
            #pragma unroll
            for (int half = 0; half < 2; half++) {
                int t = 2 * j + half;
                int c = 8 * t + cq;
                float b0 = S->bG1[c], b1 = S->bG1[c + 1];
                float u00 = fmaxf(acc[t][0] + b0, 0.f), u01 = fmaxf(acc[t][1] + b1, 0.f);
                float u10 = fmaxf(acc[t][2] + b0, 0.f), u11 = fmaxf(acc[t][3] + b1, 0.f);
                spack(u00, u01, ah[j][2 * half], al[j][2 * half]);
                spack(u10, u11, ah[j][2 * half + 1], al[j][2 * half + 1]);
            }
        }
        #pragma unroll
        for (int t = 0; t < 8; t++) { acc[t][0] = acc[t][1] = acc[t][2] = acc[t][3] = 0.f; }
        run_stage(acc, ah, al, &S->bf[2][0], lane);

        // ---- prefetch next iteration's xyz (uses new pi0/pi1) ----
        if (mn < NPTS) {
            const int nbase = (mn >> 13) * NN;
            pxc = xyz[3 * mn]; pyc = xyz[3 * mn + 1]; pzc = xyz[3 * mn + 2];
            const float* n0 = xyz + (size_t)(nbase + pi0) * 3;
            const float* n1 = xyz + (size_t)(nbase + pi1) * 3;
            pn0x = n0[0]; pn0y = n0[1]; pn0z = n0[2];
            pn1x = n1[0]; pn1y = n1[1]; pn1z = n1[2];
        }

        // ---- softmax over neighbors (no max subtraction; fp32 exp safe) ----
        {
            const float* Vr0 = g_QKV[2] + (size_t)(base + i0) * DM;
            const float* Vr1 = g_QKV[2] + (size_t)(base + i1) * DM;
            float* ao = attn_out + (size_t)m * (KNN * DM);
            float* ro = g_res + (size_t)m * DM;
            #pragma unroll
            for (int t = 0; t < 8; t++) {
                int c = 8 * t + cq;
                float b0 = S->bG2[c], b1 = S->bG2[c + 1];
                float e00 = __expf((acc[t][0] + b0) * 0.125f);
                float e01 = __expf((acc[t][1] + b1) * 0.125f);
                float e10 = __expf((acc[t][2] + b0) * 0.125f);
                float e11 = __expf((acc[t][3] + b1) * 0.125f);
                float s0 = e00 + e10, s1 = e01 + e11;
                #pragma unroll
                for (int o = 4; o < 32; o <<= 1) {
                    s0 += __shfl_xor_sync(0xffffffffu, s0, o);
                    s1 += __shfl_xor_sync(0xffffffffu, s1, o);
                }
                float inv0 = frcp(s0), inv1 = frcp(s1);
                float a00 = e00 * inv0, a01 = e01 * inv1;
                float a10 = e10 * inv0, a11 = e11 * inv1;
                *(float2*)(ao + r0 * DM + c) = make_float2(a00, a01);
                *(float2*)(ao + r1 * DM + c) = make_float2(a10, a11);
                float2 v0 = *(const float2*)(Vr0 + c);
                float2 v1 = *(const float2*)(Vr1 + c);
                float rc0 = a00 * (v0.x + pos[t][0]) + a10 * (v1.x + pos[t][2]);
                float rc1 = a01 * (v0.y + pos[t][1]) + a11 * (v1.y + pos[t][3]);
                #pragma unroll
                for (int o = 4; o < 32; o <<= 1) {
                    rc0 += __shfl_xor_sync(0xffffffffu, rc0, o);
                    rc1 += __shfl_xor_sync(0xffffffffu, rc1, o);
                }
                if (lane < 4) *(float2*)(ro + c) = make_float2(rc0, rc1);
            }
        }
    }
}

// ================= launch =================
extern "C" void kernel_launch(void* const* d_in, const int* in_sizes, int n_in,
                              void* d_out, int out_size) {
    const float* xyz      = (const float*)d_in[0];
    const float* features = (const float*)d_in[1];
    const int*   knn      = (const int*)d_in[2];
    const float* fc1_w    = (const float*)d_in[3];
    const float* fc1_b    = (const float*)d_in[4];
    const float* fc2_w    = (const float*)d_in[5];
    const float* fc2_b    = (const float*)d_in[6];
    const float* d1_w     = (const float*)d_in[7];
    const float* d1_b     = (const float*)d_in[8];
    const float* d2_w     = (const float*)d_in[9];
    const float* d2_b     = (const float*)d_in[10];
    const float* g1_w     = (const float*)d_in[11];
    const float* g1_b     = (const float*)d_in[12];
    const float* g2_w     = (const float*)d_in[13];
    const float* g2_b     = (const float*)d_in[14];
    const float* wq       = (const float*)d_in[15];
    const float* wk       = (const float*)d_in[16];
    const float* wv       = (const float*)d_in[17];
    float* out = (float*)d_out;

    prep_kernel<<<29, 256>>>(fc1_w, fc1_b, wq, wk, wv, d2_w, g1_w, g2_w, fc2_w);

    cudaFuncSetAttribute(qkv3_kernel, cudaFuncAttributeMaxDynamicSharedMemorySize, (int)sizeof(SQ));
    qkv3_kernel<<<NPTS / 128, 256, sizeof(SQ)>>>(features);

    cudaFuncSetAttribute(main_kernel, cudaFuncAttributeMaxDynamicSharedMemorySize, (int)sizeof(SMemM));
    main_kernel<<<296, 256, sizeof(SMemM)>>>(xyz, knn, d1_w, d1_b, d2_b, g1_b, g2_b, out);

    cudaFuncSetAttribute(fc2_kernel, cudaFuncAttributeMaxDynamicSharedMemorySize, (int)sizeof(SF));
    fc2_kernel<<<NPTS / 128, 256, sizeof(SF)>>>(fc2_b, features, out);
}